// round 10
// baseline (speedup 1.0000x reference)
#include <cuda_runtime.h>
#include <stdint.h>

// Problem constants
#define B_     16
#define N_     4096
#define TOTAL  (B_ * N_)      // 65536 tokens
#define DIM_   1024
#define E_     64
#define T_     8

#define BM 128
#define BKC 64
#define NCHUNK (DIM_ / BKC)    // 16
#define NTILES ((TOTAL / BM) + T_)   // 520
#define PERM_CAP (NTILES * BM)

#define XSTRIDE 144            // 72 bf16 per row: ldmatrix conflict-free
#define WSTRIDE 144
#define WWORDS  36
#define WCHUNK_WORDS (E_ * WWORDS)   // 2304 words; one image = 9216 B
#define WIMG    9216
#define WBUF    (2 * WIMG)           // hi+lo = 18432 per W stage

#define OFF_XHI  0                   // [128][72] bf16 = 18432
#define OFF_XLO  18432
#define OFF_W    36864               // 2 x (hi+lo) = 36864
#define OFF_SROW 73728               // 128 ints
#define SMEM_TOTAL 74240

#define CNT_BLOCKS 64                // count/scatter blocks (1024 tokens each)
#define WPREP_BLOCKS 1024

// ---------------- device scratch ----------------
__device__ int g_partial[CNT_BLOCKS * T_];     // per-block head counts
__device__ int g_blockBase[CNT_BLOCKS * T_];   // exclusive prefix per head
__device__ int g_counts[T_];
__device__ int g_paddedOff[T_ + 1];
__device__ int g_perm[PERM_CAP];
__device__ __align__(16) uint32_t g_Whi[T_ * NCHUNK * WCHUNK_WORDS];
__device__ __align__(16) uint32_t g_Wlo[T_ * NCHUNK * WCHUNK_WORDS];

// ---------------- helpers ----------------
__device__ __forceinline__ uint32_t smem_u32(const void* p) {
    uint32_t a;
    asm("{ .reg .u64 t; cvta.to.shared.u64 t, %1; cvt.u32.u64 %0, t; }" : "=r"(a) : "l"(p));
    return a;
}

__device__ __forceinline__ void split2(float a, float b, uint32_t& hi, uint32_t& lo) {
    asm("cvt.rn.bf16x2.f32 %0, %1, %2;" : "=r"(hi) : "f"(b), "f"(a));
    float ha = __uint_as_float(hi << 16);
    float hb = __uint_as_float(hi & 0xffff0000u);
    float ra = a - ha, rb = b - hb;
    asm("cvt.rn.bf16x2.f32 %0, %1, %2;" : "=r"(lo) : "f"(rb), "f"(ra));
}

__device__ __forceinline__ void ldsm4(uint32_t addr, uint32_t* r) {
    asm volatile("ldmatrix.sync.aligned.m8n8.x4.shared.b16 {%0,%1,%2,%3}, [%4];"
                 : "=r"(r[0]), "=r"(r[1]), "=r"(r[2]), "=r"(r[3]) : "r"(addr));
}

__device__ __forceinline__ void mma16816(float* c, const uint32_t* a,
                                         uint32_t b0, uint32_t b1) {
    asm volatile(
        "mma.sync.aligned.m16n8k16.row.col.f32.bf16.bf16.f32 "
        "{%0,%1,%2,%3}, {%4,%5,%6,%7}, {%8,%9}, {%0,%1,%2,%3};"
        : "+f"(c[0]), "+f"(c[1]), "+f"(c[2]), "+f"(c[3])
        : "r"(a[0]), "r"(a[1]), "r"(a[2]), "r"(a[3]), "r"(b0), "r"(b1));
}

__device__ __forceinline__ void cp_async16(uint32_t saddr, const void* gaddr) {
    asm volatile("cp.async.cg.shared.global [%0], [%1], 16;"
                 :: "r"(saddr), "l"(gaddr));
}
#define CP_COMMIT() asm volatile("cp.async.commit_group;" ::: "memory")
#define CP_WAIT0()  asm volatile("cp.async.wait_group 0;" ::: "memory")

// ---------------- aux: combined count (blocks 0..63) + wprep (rest) ----------------
__global__ void prep_kernel(const int* __restrict__ idx, const float* __restrict__ W) {
    if (blockIdx.x < CNT_BLOCKS) {
        // ---- count: 1024 tokens per block, no global atomics ----
        __shared__ int s[T_];
        if (threadIdx.x < T_) s[threadIdx.x] = 0;
        __syncthreads();
        int i = blockIdx.x * 256 + threadIdx.x;
        int4 v = ((const int4*)idx)[i];
        int lane = threadIdx.x & 31;
#pragma unroll
        for (int q = 0; q < 4; q++) {
            int h = ((q == 0) ? v.x : (q == 1) ? v.y : (q == 2) ? v.z : v.w) & 7;
            unsigned mask = __match_any_sync(0xffffffffu, h);
            if ((__ffs(mask) - 1) == lane) atomicAdd(&s[h], __popc(mask));
        }
        __syncthreads();
        if (threadIdx.x < T_)
            g_partial[blockIdx.x * T_ + threadIdx.x] = s[threadIdx.x];
    } else {
        // ---- wprep: pre-split W into per-chunk [n][k] bf16 hi/lo images ----
        int i = (blockIdx.x - CNT_BLOCKS) * 256 + threadIdx.x;
        int kp = i & 31;
        int n  = (i >> 5) & 63;
        int c  = (i >> 11) & 15;
        int h  = i >> 15;
        int k  = c * BKC + 2 * kp;
        float a = W[((size_t)h * DIM_ + k) * E_ + n];
        float b = W[((size_t)h * DIM_ + k + 1) * E_ + n];
        uint32_t hi, lo;
        split2(a, b, hi, lo);
        size_t dst = ((size_t)(h * NCHUNK + c) * E_ + n) * WWORDS + kp;
        g_Whi[dst] = hi;
        g_Wlo[dst] = lo;
    }
}

// ---------------- scan: per-head totals + padded offsets + per-block bases ----------------
__global__ void scan_kernel() {
    // 8 threads, one per head: sequential prefix over 64 blocks
    int h = threadIdx.x;
    if (h < T_) {
        int run = 0;
        for (int b = 0; b < CNT_BLOCKS; b++) {
            g_blockBase[b * T_ + h] = run;
            run += g_partial[b * T_ + h];
        }
        g_counts[h] = run;
    }
    __syncthreads();
    if (h == 0) {
        int off = 0;
        for (int hh = 0; hh < T_; hh++) {
            g_paddedOff[hh] = off;
            off += ((g_counts[hh] + BM - 1) / BM) * BM;
        }
        g_paddedOff[T_] = off;
    }
}

// ---------------- scatter: deterministic bases, smem-local ranks ----------------
__global__ void scatter_kernel(const int* __restrict__ idx) {
    __shared__ int scnt[T_], sbase[T_];
    int t = threadIdx.x;
    int lane = t & 31;
    if (t < T_) scnt[t] = 0;
    __syncthreads();
    int i = blockIdx.x * 256 + t;
    int4 v = ((const int4*)idx)[i];
    int hq[4], rq[4];
#pragma unroll
    for (int q = 0; q < 4; q++) {
        int h = ((q == 0) ? v.x : (q == 1) ? v.y : (q == 2) ? v.z : v.w) & 7;
        unsigned mask = __match_any_sync(0xffffffffu, h);
        int leader = __ffs(mask) - 1;
        int rank = __popc(mask & ((1u << lane) - 1u));
        int base = 0;
        if (lane == leader) base = atomicAdd(&scnt[h], __popc(mask));
        base = __shfl_sync(0xffffffffu, base, leader);
        hq[q] = h;
        rq[q] = base + rank;
    }
    __syncthreads();
    if (t < T_) sbase[t] = g_paddedOff[t] + g_blockBase[blockIdx.x * T_ + t];
    __syncthreads();
#pragma unroll
    for (int q = 0; q < 4; q++)
        g_perm[sbase[hq[q]] + rq[q]] = i * 4 + q;
}

// ---------------- pipelined HMMA GEMM (R7 skeleton, ldgX reordered) ----------------
__global__ __launch_bounds__(256, 2)
void gemm_mma(const float* __restrict__ X,
              const float* __restrict__ bias,
              float* __restrict__ out)
{
    const int tileBase = blockIdx.x * BM;
    if (tileBase >= g_paddedOff[T_]) return;

    int head = 0;
    while (g_paddedOff[head + 1] <= tileBase) head++;

    extern __shared__ char sm[];
    const uint32_t sbase = smem_u32(sm);
    int* srow = (int*)(sm + OFF_SROW);

    const int tid = threadIdx.x;
    const int wid = tid >> 5;
    const int lane = tid & 31;
    const int wm = wid & 3;        // M block (32 rows)
    const int wn = wid >> 2;       // N block (32 cols)

    const int vcnt = g_counts[head] - (tileBase - g_paddedOff[head]);
    if (tid < BM) srow[tid] = (tid < vcnt) ? g_perm[tileBase + tid] : -1;
    __syncthreads();

    // ---- ldmatrix lane offsets (m32n32 warp tile) ----
    uint32_t aOff[2];
#pragma unroll
    for (int t = 0; t < 2; t++) {
        uint32_t r = 32 * wm + 16 * t + (lane & 7) + ((lane >> 3) & 1) * 8;
        aOff[t] = r * XSTRIDE + (lane >> 4) * 16;
    }
    uint32_t bOff[2];
#pragma unroll
    for (int p = 0; p < 2; p++) {
        uint32_t r = 32 * wn + 16 * p + ((lane >> 4) << 3) + (lane & 7);
        bOff[p] = r * WSTRIDE + ((lane >> 3) & 1) * 16;
    }

    // ---- X stager mapping + cached tokens ----
    const int j2 = tid & 7;           // 8-float k group
    const int rb = tid >> 3;          // row base 0..31
    int xtok[4];
#pragma unroll
    for (int p = 0; p < 4; p++) xtok[p] = srow[rb + 32 * p];

    const uint32_t wSrcBase = (uint32_t)(head * NCHUNK) * WCHUNK_WORDS;

    float acc[32];
#pragma unroll
    for (int i = 0; i < 32; i++) acc[i] = 0.0f;

    char* xhi = sm + OFF_XHI;
    char* xlo = sm + OFF_XLO;

    float4 pf[8];

    auto ldgX = [&](int c) {
        const int k0 = c * BKC;
#pragma unroll
        for (int p = 0; p < 4; p++) {
            if (xtok[p] >= 0) {
                const float4* xp = (const float4*)(X + (size_t)xtok[p] * DIM_ + k0 + j2 * 8);
                pf[2 * p] = xp[0]; pf[2 * p + 1] = xp[1];
            } else {
                pf[2 * p] = make_float4(0.f, 0.f, 0.f, 0.f);
                pf[2 * p + 1] = pf[2 * p];
            }
        }
    };
    auto cpW = [&](int c) {
        const uint32_t ws = wSrcBase + c * WCHUNK_WORDS;
        const uint4* shi = (const uint4*)(g_Whi + ws);
        const uint4* slo = (const uint4*)(g_Wlo + ws);
        uint32_t wd = sbase + OFF_W + (c & 1) * WBUF;
#pragma unroll
        for (int i = tid; i < WIMG / 16; i += 256) {
            cp_async16(wd + i * 16, shi + i);
            cp_async16(wd + WIMG + i * 16, slo + i);
        }
        CP_COMMIT();
    };

    // prologue: X chunk 0 into regs, W chunk 0 via cp.async
    ldgX(0);
    cpW(0);

    for (int chunk = 0; chunk < NCHUNK; chunk++) {
        // ---- convert prefetched X regs -> smem ----
#pragma unroll
        for (int p = 0; p < 4; p++) {
            uint32_t h0, h1, h2, h3, l0, l1, l2, l3;
            float4 v0 = pf[2 * p], v1 = pf[2 * p + 1];
            split2(v0.x, v0.y, h0, l0);
            split2(v0.z, v0.w, h1, l1);
            split2(v1.x, v1.y, h2, l2);
            split2(v1.z, v1.w, h3, l3);
            uint32_t off = (uint32_t)((rb + 32 * p) * XSTRIDE + j2 * 16);
            *(uint4*)(xhi + off) = make_uint4(h0, h1, h2, h3);
            *(uint4*)(xlo + off) = make_uint4(l0, l1, l2, l3);
        }

        // pf dead after STS: issue next chunk's X loads before the barrier
        if (chunk + 1 < NCHUNK) ldgX(chunk + 1);

        CP_WAIT0();            // this chunk's W copy done
        __syncthreads();       // all STS + cp.async data visible

        if (chunk + 1 < NCHUNK) cpW(chunk + 1);

        // ---- HMMA on current buffers (m32n32 per warp) ----
        const uint32_t wb = sbase + OFF_W + (chunk & 1) * WBUF;
#pragma unroll
        for (int ks = 0; ks < 4; ks++) {
            uint32_t ah[2][4], al[2][4];
#pragma unroll
            for (int t = 0; t < 2; t++) {
                ldsm4(sbase + OFF_XHI + aOff[t] + ks * 32, ah[t]);
                ldsm4(sbase + OFF_XLO + aOff[t] + ks * 32, al[t]);
            }
#pragma unroll
            for (int p = 0; p < 2; p++) {
                uint32_t bh[4], bl[4];
                ldsm4(wb + bOff[p] + ks * 32, bh);
                ldsm4(wb + WIMG + bOff[p] + ks * 32, bl);
#pragma unroll
                for (int t = 0; t < 2; t++) {
                    float* c0 = acc + (t * 4 + 2 * p) * 4;
                    float* c1 = acc + (t * 4 + 2 * p + 1) * 4;
                    mma16816(c0, ah[t], bh[0], bh[1]);
                    mma16816(c0, ah[t], bl[0], bl[1]);
                    mma16816(c0, al[t], bh[0], bh[1]);
                    mma16816(c1, ah[t], bh[2], bh[3]);
                    mma16816(c1, ah[t], bl[2], bl[3]);
                    mma16816(c1, al[t], bh[2], bh[3]);
                }
            }
        }
        __syncthreads();   // MMA done before next chunk's STS overwrites X buf
    }

    // ---- epilogue: bias + scatter stores ----
    const float* bh = bias + head * E_;
    const int e0 = 2 * (lane & 3);
#pragma unroll
    for (int t = 0; t < 2; t++) {
        int r1 = 32 * wm + 16 * t + (lane >> 2);
        int tok1 = srow[r1];
        int tok2 = srow[r1 + 8];
#pragma unroll
        for (int q = 0; q < 4; q++) {
            int e = 32 * wn + 8 * q + e0;
            float be0 = bh[e], be1 = bh[e + 1];
            const float* a = acc + (t * 4 + q) * 4;
            if (tok1 >= 0)
                *(float2*)(out + (size_t)tok1 * E_ + e) = make_float2(a[0] + be0, a[1] + be1);
            if (tok2 >= 0)
                *(float2*)(out + (size_t)tok2 * E_ + e) = make_float2(a[2] + be0, a[3] + be1);
        }
    }
}

// ---------------- launch ----------------
extern "C" void kernel_launch(void* const* d_in, const int* in_sizes, int n_in,
                              void* d_out, int out_size)
{
    const float* X    = (const float*)d_in[0];
    const int*   idx  = (const int*)d_in[1];     // int32 (JAX demotes int64)
    const float* W    = (const float*)d_in[2];
    const float* bias = (const float*)d_in[3];
    float*       out  = (float*)d_out;

    static int attr_set = 0;
    if (!attr_set) {
        cudaFuncSetAttribute(gemm_mma, cudaFuncAttributeMaxDynamicSharedMemorySize, SMEM_TOTAL);
        attr_set = 1;
    }

    prep_kernel<<<CNT_BLOCKS + WPREP_BLOCKS, 256>>>(idx, W);
    scan_kernel<<<1, 32>>>();
    scatter_kernel<<<CNT_BLOCKS, 256>>>(idx);
    gemm_mma<<<NTILES, 256, SMEM_TOTAL>>>(X, bias, out);
}

// round 11
// speedup vs baseline: 1.1342x; 1.1342x over previous
#include <cuda_runtime.h>
#include <stdint.h>

// Problem constants
#define B_     16
#define N_     4096
#define TOTAL  (B_ * N_)      // 65536 tokens
#define DIM_   1024
#define E_     64
#define T_     8

#define BM 128
#define BKC 64
#define NCHUNK (DIM_ / BKC)    // 16
#define NTILES ((TOTAL / BM) + T_)   // 520
#define PERM_CAP (NTILES * BM)

#define XSTRIDE 144            // 72 bf16 per row: ldmatrix conflict-free
#define WSTRIDE 144
#define WWORDS  36
#define WCHUNK_WORDS (E_ * WWORDS)   // 2304 words; one image = 9216 B
#define WIMG    9216
#define WBUF    (2 * WIMG)           // hi+lo = 18432 per W stage

#define OFF_XHI  0                   // [128][72] bf16 = 18432
#define OFF_XLO  18432
#define OFF_W    36864               // 2 x (hi+lo) = 36864
#define OFF_SROW 73728               // 128 ints
#define SMEM_TOTAL 74240

#define CNT_BLOCKS 64                // count/scatter blocks (1024 tokens each)
#define WPREP_BLOCKS 1024

// ---------------- device scratch ----------------
__device__ int g_partial[CNT_BLOCKS * T_];     // per-block head counts
__device__ int g_blockBase[CNT_BLOCKS * T_];   // exclusive prefix per head
__device__ int g_counts[T_];
__device__ int g_paddedOff[T_ + 1];
__device__ int g_perm[PERM_CAP];
__device__ __align__(16) uint32_t g_Whi[T_ * NCHUNK * WCHUNK_WORDS];
__device__ __align__(16) uint32_t g_Wlo[T_ * NCHUNK * WCHUNK_WORDS];

// ---------------- helpers ----------------
__device__ __forceinline__ uint32_t smem_u32(const void* p) {
    uint32_t a;
    asm("{ .reg .u64 t; cvta.to.shared.u64 t, %1; cvt.u32.u64 %0, t; }" : "=r"(a) : "l"(p));
    return a;
}

__device__ __forceinline__ void split2(float a, float b, uint32_t& hi, uint32_t& lo) {
    asm("cvt.rn.bf16x2.f32 %0, %1, %2;" : "=r"(hi) : "f"(b), "f"(a));
    float ha = __uint_as_float(hi << 16);
    float hb = __uint_as_float(hi & 0xffff0000u);
    float ra = a - ha, rb = b - hb;
    asm("cvt.rn.bf16x2.f32 %0, %1, %2;" : "=r"(lo) : "f"(rb), "f"(ra));
}

__device__ __forceinline__ void ldsm4(uint32_t addr, uint32_t* r) {
    asm volatile("ldmatrix.sync.aligned.m8n8.x4.shared.b16 {%0,%1,%2,%3}, [%4];"
                 : "=r"(r[0]), "=r"(r[1]), "=r"(r[2]), "=r"(r[3]) : "r"(addr));
}

__device__ __forceinline__ void mma16816(float* c, const uint32_t* a,
                                         uint32_t b0, uint32_t b1) {
    asm volatile(
        "mma.sync.aligned.m16n8k16.row.col.f32.bf16.bf16.f32 "
        "{%0,%1,%2,%3}, {%4,%5,%6,%7}, {%8,%9}, {%0,%1,%2,%3};"
        : "+f"(c[0]), "+f"(c[1]), "+f"(c[2]), "+f"(c[3])
        : "r"(a[0]), "r"(a[1]), "r"(a[2]), "r"(a[3]), "r"(b0), "r"(b1));
}

__device__ __forceinline__ void cp_async16(uint32_t saddr, const void* gaddr) {
    asm volatile("cp.async.cg.shared.global [%0], [%1], 16;"
                 :: "r"(saddr), "l"(gaddr));
}
#define CP_COMMIT() asm volatile("cp.async.commit_group;" ::: "memory")
#define CP_WAIT0()  asm volatile("cp.async.wait_group 0;" ::: "memory")

// ---------------- aux: combined count (blocks 0..63) + wprep (rest) ----------------
__global__ void prep_kernel(const int* __restrict__ idx, const float* __restrict__ W) {
    if (blockIdx.x < CNT_BLOCKS) {
        // ---- count: 1024 tokens per block, no global atomics ----
        __shared__ int s[T_];
        if (threadIdx.x < T_) s[threadIdx.x] = 0;
        __syncthreads();
        int i = blockIdx.x * 256 + threadIdx.x;
        int4 v = ((const int4*)idx)[i];
        int lane = threadIdx.x & 31;
#pragma unroll
        for (int q = 0; q < 4; q++) {
            int h = ((q == 0) ? v.x : (q == 1) ? v.y : (q == 2) ? v.z : v.w) & 7;
            unsigned mask = __match_any_sync(0xffffffffu, h);
            if ((__ffs(mask) - 1) == lane) atomicAdd(&s[h], __popc(mask));
        }
        __syncthreads();
        if (threadIdx.x < T_)
            g_partial[blockIdx.x * T_ + threadIdx.x] = s[threadIdx.x];
    } else {
        // ---- wprep: coalesced reads (consecutive threads -> consecutive n) ----
        int i = (blockIdx.x - CNT_BLOCKS) * 256 + threadIdx.x;
        int n  = i & 63;
        int kp = (i >> 6) & 31;
        int c  = (i >> 11) & 15;
        int h  = i >> 15;
        int k  = c * BKC + 2 * kp;
        float a = W[((size_t)h * DIM_ + k) * E_ + n];
        float b = W[((size_t)h * DIM_ + k + 1) * E_ + n];
        uint32_t hi, lo;
        split2(a, b, hi, lo);
        size_t dst = ((size_t)(h * NCHUNK + c) * E_ + n) * WWORDS + kp;
        g_Whi[dst] = hi;
        g_Wlo[dst] = lo;
    }
}

// ---------------- scan: parallel warp-scan (one block, 8 warps) ----------------
__global__ void scan_kernel() {
    int wid = threadIdx.x >> 5;     // head
    int lane = threadIdx.x & 31;
    if (wid < T_) {
        // blocks lane and lane+32 for head wid
        int p0 = g_partial[lane * T_ + wid];
        int p1 = g_partial[(lane + 32) * T_ + wid];
        // inclusive shuffle scan of p0
        int s0 = p0;
#pragma unroll
        for (int d = 1; d < 32; d <<= 1) {
            int v = __shfl_up_sync(0xffffffffu, s0, d);
            if (lane >= d) s0 += v;
        }
        int tot0 = __shfl_sync(0xffffffffu, s0, 31);
        int s1 = p1;
#pragma unroll
        for (int d = 1; d < 32; d <<= 1) {
            int v = __shfl_up_sync(0xffffffffu, s1, d);
            if (lane >= d) s1 += v;
        }
        g_blockBase[lane * T_ + wid] = s0 - p0;                 // exclusive
        g_blockBase[(lane + 32) * T_ + wid] = tot0 + s1 - p1;
        if (lane == 31) g_counts[wid] = tot0 + s1;
    }
    __syncthreads();
    if (threadIdx.x == 0) {
        int off = 0;
        for (int hh = 0; hh < T_; hh++) {
            g_paddedOff[hh] = off;
            off += ((g_counts[hh] + BM - 1) / BM) * BM;
        }
        g_paddedOff[T_] = off;
    }
}

// ---------------- scatter: deterministic bases, smem-local ranks ----------------
__global__ void scatter_kernel(const int* __restrict__ idx) {
    __shared__ int scnt[T_], sbase[T_];
    int t = threadIdx.x;
    int lane = t & 31;
    if (t < T_) scnt[t] = 0;
    __syncthreads();
    int i = blockIdx.x * 256 + t;
    int4 v = ((const int4*)idx)[i];
    int hq[4], rq[4];
#pragma unroll
    for (int q = 0; q < 4; q++) {
        int h = ((q == 0) ? v.x : (q == 1) ? v.y : (q == 2) ? v.z : v.w) & 7;
        unsigned mask = __match_any_sync(0xffffffffu, h);
        int leader = __ffs(mask) - 1;
        int rank = __popc(mask & ((1u << lane) - 1u));
        int base = 0;
        if (lane == leader) base = atomicAdd(&scnt[h], __popc(mask));
        base = __shfl_sync(0xffffffffu, base, leader);
        hq[q] = h;
        rq[q] = base + rank;
    }
    __syncthreads();
    if (t < T_) sbase[t] = g_paddedOff[t] + g_blockBase[blockIdx.x * T_ + t];
    __syncthreads();
#pragma unroll
    for (int q = 0; q < 4; q++)
        g_perm[sbase[hq[q]] + rq[q]] = i * 4 + q;
}

// ---------------- pipelined HMMA GEMM (unchanged from measured 84.9us) ----------------
__global__ __launch_bounds__(256, 2)
void gemm_mma(const float* __restrict__ X,
              const float* __restrict__ bias,
              float* __restrict__ out)
{
    const int tileBase = blockIdx.x * BM;
    if (tileBase >= g_paddedOff[T_]) return;

    int head = 0;
    while (g_paddedOff[head + 1] <= tileBase) head++;

    extern __shared__ char sm[];
    const uint32_t sbase = smem_u32(sm);
    int* srow = (int*)(sm + OFF_SROW);

    const int tid = threadIdx.x;
    const int wid = tid >> 5;
    const int lane = tid & 31;
    const int wm = wid & 3;        // M block (32 rows)
    const int wn = wid >> 2;       // N block (32 cols)

    const int vcnt = g_counts[head] - (tileBase - g_paddedOff[head]);
    if (tid < BM) srow[tid] = (tid < vcnt) ? g_perm[tileBase + tid] : -1;
    __syncthreads();

    uint32_t aOff[2];
#pragma unroll
    for (int t = 0; t < 2; t++) {
        uint32_t r = 32 * wm + 16 * t + (lane & 7) + ((lane >> 3) & 1) * 8;
        aOff[t] = r * XSTRIDE + (lane >> 4) * 16;
    }
    uint32_t bOff[2];
#pragma unroll
    for (int p = 0; p < 2; p++) {
        uint32_t r = 32 * wn + 16 * p + ((lane >> 4) << 3) + (lane & 7);
        bOff[p] = r * WSTRIDE + ((lane >> 3) & 1) * 16;
    }

    const int j2 = tid & 7;
    const int rb = tid >> 3;
    int xtok[4];
#pragma unroll
    for (int p = 0; p < 4; p++) xtok[p] = srow[rb + 32 * p];

    const uint32_t wSrcBase = (uint32_t)(head * NCHUNK) * WCHUNK_WORDS;

    float acc[32];
#pragma unroll
    for (int i = 0; i < 32; i++) acc[i] = 0.0f;

    char* xhi = sm + OFF_XHI;
    char* xlo = sm + OFF_XLO;

    float4 pf[8];

    auto ldgX = [&](int c) {
        const int k0 = c * BKC;
#pragma unroll
        for (int p = 0; p < 4; p++) {
            if (xtok[p] >= 0) {
                const float4* xp = (const float4*)(X + (size_t)xtok[p] * DIM_ + k0 + j2 * 8);
                pf[2 * p] = xp[0]; pf[2 * p + 1] = xp[1];
            } else {
                pf[2 * p] = make_float4(0.f, 0.f, 0.f, 0.f);
                pf[2 * p + 1] = pf[2 * p];
            }
        }
    };
    auto cpW = [&](int c) {
        const uint32_t ws = wSrcBase + c * WCHUNK_WORDS;
        const uint4* shi = (const uint4*)(g_Whi + ws);
        const uint4* slo = (const uint4*)(g_Wlo + ws);
        uint32_t wd = sbase + OFF_W + (c & 1) * WBUF;
#pragma unroll
        for (int i = tid; i < WIMG / 16; i += 256) {
            cp_async16(wd + i * 16, shi + i);
            cp_async16(wd + WIMG + i * 16, slo + i);
        }
        CP_COMMIT();
    };

    ldgX(0);
    cpW(0);

    for (int chunk = 0; chunk < NCHUNK; chunk++) {
#pragma unroll
        for (int p = 0; p < 4; p++) {
            uint32_t h0, h1, h2, h3, l0, l1, l2, l3;
            float4 v0 = pf[2 * p], v1 = pf[2 * p + 1];
            split2(v0.x, v0.y, h0, l0);
            split2(v0.z, v0.w, h1, l1);
            split2(v1.x, v1.y, h2, l2);
            split2(v1.z, v1.w, h3, l3);
            uint32_t off = (uint32_t)((rb + 32 * p) * XSTRIDE + j2 * 16);
            *(uint4*)(xhi + off) = make_uint4(h0, h1, h2, h3);
            *(uint4*)(xlo + off) = make_uint4(l0, l1, l2, l3);
        }

        if (chunk + 1 < NCHUNK) ldgX(chunk + 1);

        CP_WAIT0();
        __syncthreads();

        if (chunk + 1 < NCHUNK) cpW(chunk + 1);

        const uint32_t wb = sbase + OFF_W + (chunk & 1) * WBUF;
#pragma unroll
        for (int ks = 0; ks < 4; ks++) {
            uint32_t ah[2][4], al[2][4];
#pragma unroll
            for (int t = 0; t < 2; t++) {
                ldsm4(sbase + OFF_XHI + aOff[t] + ks * 32, ah[t]);
                ldsm4(sbase + OFF_XLO + aOff[t] + ks * 32, al[t]);
            }
#pragma unroll
            for (int p = 0; p < 2; p++) {
                uint32_t bh[4], bl[4];
                ldsm4(wb + bOff[p] + ks * 32, bh);
                ldsm4(wb + WIMG + bOff[p] + ks * 32, bl);
#pragma unroll
                for (int t = 0; t < 2; t++) {
                    float* c0 = acc + (t * 4 + 2 * p) * 4;
                    float* c1 = acc + (t * 4 + 2 * p + 1) * 4;
                    mma16816(c0, ah[t], bh[0], bh[1]);
                    mma16816(c0, ah[t], bl[0], bl[1]);
                    mma16816(c0, al[t], bh[0], bh[1]);
                    mma16816(c1, ah[t], bh[2], bh[3]);
                    mma16816(c1, ah[t], bl[2], bl[3]);
                    mma16816(c1, al[t], bh[2], bh[3]);
                }
            }
        }
        __syncthreads();
    }

    const float* bh = bias + head * E_;
    const int e0 = 2 * (lane & 3);
#pragma unroll
    for (int t = 0; t < 2; t++) {
        int r1 = 32 * wm + 16 * t + (lane >> 2);
        int tok1 = srow[r1];
        int tok2 = srow[r1 + 8];
#pragma unroll
        for (int q = 0; q < 4; q++) {
            int e = 32 * wn + 8 * q + e0;
            float be0 = bh[e], be1 = bh[e + 1];
            const float* a = acc + (t * 4 + q) * 4;
            if (tok1 >= 0)
                *(float2*)(out + (size_t)tok1 * E_ + e) = make_float2(a[0] + be0, a[1] + be1);
            if (tok2 >= 0)
                *(float2*)(out + (size_t)tok2 * E_ + e) = make_float2(a[2] + be0, a[3] + be1);
        }
    }
}

// ---------------- launch ----------------
extern "C" void kernel_launch(void* const* d_in, const int* in_sizes, int n_in,
                              void* d_out, int out_size)
{
    const float* X    = (const float*)d_in[0];
    const int*   idx  = (const int*)d_in[1];     // int32 (JAX demotes int64)
    const float* W    = (const float*)d_in[2];
    const float* bias = (const float*)d_in[3];
    float*       out  = (float*)d_out;

    static int attr_set = 0;
    if (!attr_set) {
        cudaFuncSetAttribute(gemm_mma, cudaFuncAttributeMaxDynamicSharedMemorySize, SMEM_TOTAL);
        attr_set = 1;
    }

    prep_kernel<<<CNT_BLOCKS + WPREP_BLOCKS, 256>>>(idx, W);
    scan_kernel<<<1, 256>>>();
    scatter_kernel<<<CNT_BLOCKS, 256>>>(idx);
    gemm_mma<<<NTILES, 256, SMEM_TOTAL>>>(X, bias, out);
}